// round 2
// baseline (speedup 1.0000x reference)
#include <cuda_runtime.h>
#include <cstdint>

using ull = unsigned long long;

#define THREADS 256
#define TILE    512          // edges per block-iteration (2 per thread, packed)
#define HID     10
#define NOUT    19
#define ST_FLOATS (TILE * NOUT)          // 9728 floats
#define ST_BYTES  (ST_FLOATS * 4)        // 38912 bytes

// ---------- packed f32x2 helpers ----------
__device__ __forceinline__ ull pack2(float lo, float hi) {
    ull r; asm("mov.b64 %0, {%1, %2};" : "=l"(r) : "f"(lo), "f"(hi)); return r;
}
__device__ __forceinline__ void unpack2(ull v, float& lo, float& hi) {
    asm("mov.b64 {%0, %1}, %2;" : "=f"(lo), "=f"(hi) : "l"(v));
}
__device__ __forceinline__ ull ffma2(ull a, ull b, ull c) {
    ull d; asm("fma.rn.f32x2 %0, %1, %2, %3;" : "=l"(d) : "l"(a), "l"(b), "l"(c)); return d;
}
__device__ __forceinline__ ull relu2(ull a) {
    float lo, hi; unpack2(a, lo, hi);
    return pack2(fmaxf(lo, 0.0f), fmaxf(hi, 0.0f));
}

__global__ __launch_bounds__(THREADS)
void edge_mlp_kernel(const float* __restrict__ src,
                     const float* __restrict__ dest,
                     const float* __restrict__ ea,
                     const float* __restrict__ u,
                     const int* __restrict__ batch,  // int32 graph ids
                     const float* __restrict__ W1,   // (4,10) row-major
                     const float* __restrict__ b1,   // (10)
                     const float* __restrict__ W2,   // (10,19) row-major
                     const float* __restrict__ b2,   // (19)
                     float* __restrict__ out,        // (E,19)
                     int E, int B, int nTiles)
{
    extern __shared__ __align__(16) char smem[];
    float* st = (float*)smem;                               // [512*19] staging
    float* su = (float*)(smem + ST_BYTES);                  // [B] u table
    const int ub = (B * 4 + 15) & ~15;
    ull* W1p = (ull*)(smem + ST_BYTES + ub);                // [40]  (w,w) pairs: [j][r]
    ull* b1p = W1p + 40;                                    // [10]
    ull* W2p = b1p + 10;                                    // [190] [k][j]
    ull* b2p = W2p + 190;                                   // [19]

    const int tid = threadIdx.x;
    const int Bm1 = B - 1;

    // ---- one-time per-block init: u table + duplicated-pair weights ----
    for (int i = tid; i < B; i += THREADS) su[i] = u[i];
    if (tid < 40) {                       // W1p[j*4+r] = (W1[r][j], W1[r][j])
        int j = tid >> 2, r = tid & 3;
        float w = W1[r * 10 + j];
        W1p[tid] = pack2(w, w);
    }
    if (tid < 10) { float v = b1[tid]; b1p[tid] = pack2(v, v); }
    if (tid < 190) {                      // W2p[k*10+j] = (W2[j][k], W2[j][k])
        int k = tid / 10, j = tid - k * 10;
        float w = W2[j * NOUT + k];
        W2p[tid] = pack2(w, w);
    }
    if (tid < NOUT) { float v = b2[tid]; b2p[tid] = pack2(v, v); }
    __syncthreads();

    const ulonglong2* W1v = (const ulonglong2*)W1p;

    for (int tile = blockIdx.x; tile < nTiles; tile += gridDim.x) {
        const int base = tile * TILE;
        const bool full = (base + TILE) <= E;

        if (full) {
            const int g0 = base + tid;
            const int g1 = g0 + THREADS;
            // coalesced loads, two edges per thread
            float s0 = src[g0],  s1 = src[g1];
            float d0 = dest[g0], d1 = dest[g1];
            float a0 = ea[g0],   a1 = ea[g1];
            int   i0 = batch[g0], i1 = batch[g1];
            i0 = min(max(i0, 0), Bm1);          // defensive clamp, cheap
            i1 = min(max(i1, 0), Bm1);
            ull S = pack2(s0, s1);
            ull D = pack2(d0, d1);
            ull A = pack2(a0, a1);
            ull U = pack2(su[i0], su[i1]);

            // stage 1: h = relu(x @ W1 + b1), packed over the 2 edges
            ull h[HID];
            #pragma unroll
            for (int j = 0; j < HID; j++) {
                ulonglong2 w01 = W1v[j * 2 + 0];   // (W1[0][j], W1[1][j]) pairs
                ulonglong2 w23 = W1v[j * 2 + 1];   // (W1[2][j], W1[3][j]) pairs
                ull acc = b1p[j];
                acc = ffma2(S, w01.x, acc);
                acc = ffma2(D, w01.y, acc);
                acc = ffma2(A, w23.x, acc);
                acc = ffma2(U, w23.y, acc);
                h[j] = relu2(acc);
            }

            // stage 2: out = h @ W2 + b2 ; stage into smem (conflict-free, stride 19)
            #pragma unroll
            for (int k = 0; k < NOUT; k++) {
                const ulonglong2* wr = (const ulonglong2*)(W2p + k * HID);
                ull acc = b2p[k];
                ulonglong2 w;
                w = wr[0]; acc = ffma2(h[0], w.x, acc); acc = ffma2(h[1], w.y, acc);
                w = wr[1]; acc = ffma2(h[2], w.x, acc); acc = ffma2(h[3], w.y, acc);
                w = wr[2]; acc = ffma2(h[4], w.x, acc); acc = ffma2(h[5], w.y, acc);
                w = wr[3]; acc = ffma2(h[6], w.x, acc); acc = ffma2(h[7], w.y, acc);
                w = wr[4]; acc = ffma2(h[8], w.x, acc); acc = ffma2(h[9], w.y, acc);
                float lo, hi; unpack2(acc, lo, hi);
                st[tid * NOUT + k]             = lo;
                st[(tid + THREADS) * NOUT + k] = hi;
            }
            __syncthreads();

            // coalesced float4 flush: 512*19 floats = 2432 float4
            float4* o4 = (float4*)(out + (size_t)base * NOUT);
            const float4* s4 = (const float4*)st;
            #pragma unroll 10
            for (int q = tid; q < ST_FLOATS / 4; q += THREADS) o4[q] = s4[q];
            __syncthreads();
        } else {
            // -------- tail tile (only when E not a multiple of 512) --------
            const float* W1f = (const float*)W1p;  // lo halves of packed pairs
            const float* b1f = (const float*)b1p;
            const float* W2f = (const float*)W2p;
            const float* b2f = (const float*)b2p;
            #pragma unroll
            for (int half = 0; half < 2; half++) {
                int row = tid + half * THREADS;
                int g = base + row;
                if (g < E) {
                    float s = src[g], d = dest[g], a = ea[g];
                    int bi = min(max(batch[g], 0), Bm1);
                    float uu = su[bi];
                    float h[HID];
                    #pragma unroll
                    for (int j = 0; j < HID; j++) {
                        float acc = b1f[j * 2];
                        acc = fmaf(s,  W1f[(j * 4 + 0) * 2], acc);
                        acc = fmaf(d,  W1f[(j * 4 + 1) * 2], acc);
                        acc = fmaf(a,  W1f[(j * 4 + 2) * 2], acc);
                        acc = fmaf(uu, W1f[(j * 4 + 3) * 2], acc);
                        h[j] = fmaxf(acc, 0.0f);
                    }
                    #pragma unroll
                    for (int k = 0; k < NOUT; k++) {
                        float acc = b2f[k * 2];
                        #pragma unroll
                        for (int j = 0; j < HID; j++)
                            acc = fmaf(h[j], W2f[(k * HID + j) * 2], acc);
                        st[row * NOUT + k] = acc;
                    }
                }
            }
            __syncthreads();
            int ve = E - base; if (ve > TILE) ve = TILE;
            size_t obase = (size_t)base * NOUT;
            for (int q = tid; q < ve * NOUT; q += THREADS) out[obase + q] = st[q];
            __syncthreads();
        }
    }
}

extern "C" void kernel_launch(void* const* d_in, const int* in_sizes, int n_in,
                              void* d_out, int out_size)
{
    const float* src   = (const float*)d_in[0];
    const float* dest  = (const float*)d_in[1];
    const float* ea    = (const float*)d_in[2];
    const float* u     = (const float*)d_in[3];
    const int*   batch = (const int*)d_in[4];      // int32 (JAX default x64 off)
    const float* W1    = (const float*)d_in[5];
    const float* b1    = (const float*)d_in[6];
    const float* W2    = (const float*)d_in[7];
    const float* b2    = (const float*)d_in[8];
    float* out = (float*)d_out;

    const int E = in_sizes[0];
    const int B = in_sizes[3];
    const int nTiles = (E + TILE - 1) / TILE;

    const int ub = (B * 4 + 15) & ~15;
    const int smemBytes = ST_BYTES + ub + (40 + 10 + 190 + 19) * 8 + 16;

    cudaFuncSetAttribute(edge_mlp_kernel,
                         cudaFuncAttributeMaxDynamicSharedMemorySize, smemBytes);

    int grid = nTiles < 1776 ? nTiles : 1776;   // ~3 CTAs/SM resident, grid-stride
    if (grid < 1) grid = 1;

    edge_mlp_kernel<<<grid, THREADS, smemBytes>>>(
        src, dest, ea, u, batch, W1, b1, W2, b2, out, E, B, nTiles);
}

// round 4
// speedup vs baseline: 1.7981x; 1.7981x over previous
#include <cuda_runtime.h>
#include <cstdint>

using ull = unsigned long long;

#define THREADS 256
#define PACKS   2              // f32x2 packs per thread (2 edges each) -> 4 edges/thread
#define TILE    1024           // THREADS * 2 * PACKS
#define HID     10
#define NOUT    19
#define ST_FLOATS (TILE * NOUT)          // 19456 floats
#define ST_BYTES  (ST_FLOATS * 4)        // 77824 bytes

// ---------- packed f32x2 helpers ----------
__device__ __forceinline__ ull pack2(float lo, float hi) {
    ull r; asm("mov.b64 %0, {%1, %2};" : "=l"(r) : "f"(lo), "f"(hi)); return r;
}
__device__ __forceinline__ void unpack2(ull v, float& lo, float& hi) {
    asm("mov.b64 {%0, %1}, %2;" : "=f"(lo), "=f"(hi) : "l"(v));
}
__device__ __forceinline__ ull ffma2(ull a, ull b, ull c) {
    ull d; asm("fma.rn.f32x2 %0, %1, %2, %3;" : "=l"(d) : "l"(a), "l"(b), "l"(c)); return d;
}
__device__ __forceinline__ ull add2(ull a, ull b) {
    ull d; asm("add.rn.f32x2 %0, %1, %2;" : "=l"(d) : "l"(a), "l"(b)); return d;
}
__device__ __forceinline__ ull relu2(ull a) {
    float lo, hi; unpack2(a, lo, hi);
    return pack2(fmaxf(lo, 0.0f), fmaxf(hi, 0.0f));
}

__global__ __launch_bounds__(THREADS, 2)
void edge_mlp_kernel(const float* __restrict__ src,
                     const float* __restrict__ dest,
                     const float* __restrict__ ea,
                     const float* __restrict__ u,
                     const int* __restrict__ batch,  // int32 graph ids
                     const float* __restrict__ W1,   // (4,10) row-major
                     const float* __restrict__ b1,   // (10)
                     const float* __restrict__ W2,   // (10,19) row-major
                     const float* __restrict__ b2,   // (19)
                     float* __restrict__ out,        // (E,19)
                     int E, int B, int nTiles)
{
    extern __shared__ __align__(16) char smem[];
    float* st = (float*)smem;                               // [1024*19] staging
    float* su = (float*)(smem + ST_BYTES);                  // [B] u table
    const int ub = (B * 4 + 15) & ~15;
    ull* W1p = (ull*)(smem + ST_BYTES + ub);                // [40]  (w,w) pairs: [j][r]
    ull* b1p = W1p + 40;                                    // [10]
    ull* W2p = b1p + 10;                                    // [190] [k][j]
    ull* b2p = W2p + 190;                                   // [19]

    const int tid = threadIdx.x;
    const int Bm1 = B - 1;

    // ---- one-time per-block init: u table + duplicated-pair weights ----
    for (int i = tid; i < B; i += THREADS) su[i] = u[i];
    if (tid < 40) {                       // W1p[j*4+r] = (W1[r][j], W1[r][j])
        int j = tid >> 2, r = tid & 3;
        float w = W1[r * 10 + j];
        W1p[tid] = pack2(w, w);
    }
    if (tid < 10) { float v = b1[tid]; b1p[tid] = pack2(v, v); }
    if (tid < 190) {                      // W2p[k*10+j] = (W2[j][k], W2[j][k])
        int k = tid / 10, j = tid - k * 10;
        float w = W2[j * NOUT + k];
        W2p[tid] = pack2(w, w);
    }
    if (tid < NOUT) { float v = b2[tid]; b2p[tid] = pack2(v, v); }
    __syncthreads();

    const ulonglong2* W1v = (const ulonglong2*)W1p;

    for (int tile = blockIdx.x; tile < nTiles; tile += gridDim.x) {
        const int base = tile * TILE;
        const bool full = (base + TILE) <= E;

        if (full) {
            // ---- front-batched coalesced loads: 4 edges/thread, 2 packs ----
            ull S[PACKS], D[PACKS], A[PACKS], U[PACKS];
            #pragma unroll
            for (int c = 0; c < PACKS; c++) {
                const int g0 = base + c * (2 * THREADS) + tid;
                const int g1 = g0 + THREADS;
                float s0 = src[g0],  s1 = src[g1];
                float d0 = dest[g0], d1 = dest[g1];
                float a0 = ea[g0],   a1 = ea[g1];
                int   i0 = batch[g0], i1 = batch[g1];
                i0 = min(max(i0, 0), Bm1);
                i1 = min(max(i1, 0), Bm1);
                S[c] = pack2(s0, s1);
                D[c] = pack2(d0, d1);
                A[c] = pack2(a0, a1);
                U[c] = pack2(su[i0], su[i1]);
            }

            // ---- stage 1: h = relu(x @ W1 + b1); weight loads shared over packs ----
            ull h[PACKS][HID];
            #pragma unroll
            for (int j = 0; j < HID; j++) {
                ulonglong2 w01 = W1v[j * 2 + 0];   // (W1[0][j]), (W1[1][j]) pairs
                ulonglong2 w23 = W1v[j * 2 + 1];   // (W1[2][j]), (W1[3][j]) pairs
                ull bj = b1p[j];
                #pragma unroll
                for (int c = 0; c < PACKS; c++) {
                    ull acc = ffma2(S[c], w01.x, bj);
                    acc = ffma2(D[c], w01.y, acc);
                    acc = ffma2(A[c], w23.x, acc);
                    acc = ffma2(U[c], w23.y, acc);
                    h[c][j] = relu2(acc);
                }
            }

            // ---- stage 2: out = h @ W2 + b2; even/odd split accumulators ----
            for (int k = 0; k < NOUT; k++) {
                const ulonglong2* wr = (const ulonglong2*)(W2p + k * HID);
                ulonglong2 w0 = wr[0], w1 = wr[1], w2 = wr[2], w3 = wr[3], w4 = wr[4];
                ull bk = b2p[k];
                #pragma unroll
                for (int c = 0; c < PACKS; c++) {
                    // even-j chain (seeded with bias) and odd-j chain (seeded 0)
                    ull accA = ffma2(h[c][0], w0.x, bk);
                    ull accB = ffma2(h[c][1], w0.y, 0ULL);   // 0ULL == (0.0f,0.0f)
                    accA = ffma2(h[c][2], w1.x, accA);
                    accB = ffma2(h[c][3], w1.y, accB);
                    accA = ffma2(h[c][4], w2.x, accA);
                    accB = ffma2(h[c][5], w2.y, accB);
                    accA = ffma2(h[c][6], w3.x, accA);
                    accB = ffma2(h[c][7], w3.y, accB);
                    accA = ffma2(h[c][8], w4.x, accA);
                    accB = ffma2(h[c][9], w4.y, accB);
                    ull acc = add2(accA, accB);
                    float lo, hi; unpack2(acc, lo, hi);
                    const int row0 = c * (2 * THREADS) + tid;
                    st[row0 * NOUT + k]           = lo;
                    st[(row0 + THREADS) * NOUT + k] = hi;
                }
            }
            __syncthreads();

            // ---- coalesced float4 flush: 1024*19 floats = 4864 float4 ----
            float4* o4 = (float4*)(out + (size_t)base * NOUT);
            const float4* s4 = (const float4*)st;
            #pragma unroll
            for (int q = 0; q < ST_FLOATS / 4 / THREADS; q++)
                o4[q * THREADS + tid] = s4[q * THREADS + tid];
            __syncthreads();
        } else {
            // -------- tail tile (E % 1024 edges) --------
            const float* W1f = (const float*)W1p;  // lo halves of packed pairs
            const float* b1f = (const float*)b1p;
            const float* W2f = (const float*)W2p;
            const float* b2f = (const float*)b2p;
            #pragma unroll
            for (int q = 0; q < 2 * PACKS; q++) {
                int row = tid + q * THREADS;
                int g = base + row;
                if (g < E) {
                    float s = src[g], d = dest[g], a = ea[g];
                    int bi = min(max(batch[g], 0), Bm1);
                    float uu = su[bi];
                    float h[HID];
                    #pragma unroll
                    for (int j = 0; j < HID; j++) {
                        float acc = b1f[j * 2];
                        acc = fmaf(s,  W1f[(j * 4 + 0) * 2], acc);
                        acc = fmaf(d,  W1f[(j * 4 + 1) * 2], acc);
                        acc = fmaf(a,  W1f[(j * 4 + 2) * 2], acc);
                        acc = fmaf(uu, W1f[(j * 4 + 3) * 2], acc);
                        h[j] = fmaxf(acc, 0.0f);
                    }
                    #pragma unroll
                    for (int k = 0; k < NOUT; k++) {
                        float acc = b2f[k * 2];
                        #pragma unroll
                        for (int j = 0; j < HID; j++)
                            acc = fmaf(h[j], W2f[(k * HID + j) * 2], acc);
                        st[row * NOUT + k] = acc;
                    }
                }
            }
            __syncthreads();
            int ve = E - base; if (ve > TILE) ve = TILE;
            size_t obase = (size_t)base * NOUT;
            for (int q = tid; q < ve * NOUT; q += THREADS) out[obase + q] = st[q];
            __syncthreads();
        }
    }
}

extern "C" void kernel_launch(void* const* d_in, const int* in_sizes, int n_in,
                              void* d_out, int out_size)
{
    const float* src   = (const float*)d_in[0];
    const float* dest  = (const float*)d_in[1];
    const float* ea    = (const float*)d_in[2];
    const float* u     = (const float*)d_in[3];
    const int*   batch = (const int*)d_in[4];      // int32
    const float* W1    = (const float*)d_in[5];
    const float* b1    = (const float*)d_in[6];
    const float* W2    = (const float*)d_in[7];
    const float* b2    = (const float*)d_in[8];
    float* out = (float*)d_out;

    const int E = in_sizes[0];
    const int B = in_sizes[3];
    const int nTiles = (E + TILE - 1) / TILE;

    const int ub = (B * 4 + 15) & ~15;
    const int smemBytes = ST_BYTES + ub + (40 + 10 + 190 + 19) * 8 + 16;

    cudaFuncSetAttribute(edge_mlp_kernel,
                         cudaFuncAttributeMaxDynamicSharedMemorySize, smemBytes);

    int grid = nTiles < 296 ? nTiles : 296;   // 2 CTAs/SM resident, grid-stride
    if (grid < 1) grid = 1;

    edge_mlp_kernel<<<grid, THREADS, smemBytes>>>(
        src, dest, ea, u, batch, W1, b1, W2, b2, out, E, B, nTiles);
}